// round 16
// baseline (speedup 1.0000x reference)
#include <cuda_runtime.h>

// FullSpikeFunction: LIF recurrence with adaptive threshold + refractory.
// x[B=16, T=4096, N=1024] fp32 -> z[B, T, N] fp32.
//
// Numerics contract (validated rel_err==0.0 R7-R14): XLA fuses the LHS fmul
// of each fadd/fsub (one-use only); the two-use spike crumb stays unfused;
// q uses f32->s32 truncation semantics. See lif_step.
//
// R15 post-mortem: rel_err 1.1e-2 was a cp.async FIFO RACE, not numerics.
// At iter g, wait_group 1 precedes the issue of G(g+2), so the newest
// outstanding commit is G(g+1) -- which wait_group 1 does NOT drain. The
// cross-group lookahead read of group g+1's first row raced the in-flight
// copy. Fix: consume ONLY group g (guaranteed landed); re-prime the
// lookahead register from bc[tid] at each group start (1 exposed LDS per
// 16 steps). Keep: 64 blocks x 256 threads (2 warps/SMSP so sibling warps
// fill chain stalls), fused z-select, SMEM 3-stage cp.async ring.

namespace {
constexpr int kB = 16;
constexpr int kT = 4096;
constexpr int kN = 1024;
constexpr int kU = 16;                     // time steps per group
constexpr int kThreads = 256;
constexpr int kLanes = kB * kN;            // 16384
constexpr int kBlocks = kLanes / kThreads; // 64
constexpr int kGroups = kT / kU;           // 256
constexpr int kBufFloats = kU * kThreads;  // 4096 floats = 16 KB per stage
}  // namespace

__device__ __forceinline__ unsigned smem_u32(const void* p) {
    unsigned r;
    asm("{ .reg .u64 t; cvta.to.shared.u64 t, %1; cvt.u32.u64 %0, t; }"
        : "=r"(r) : "l"(p));
    return r;
}

// One time-step, exact reference rounding (validated rel_err == 0.0).
__device__ __forceinline__ float lif_step(float xt, float& u, float& bb,
                                          int& q, float& zprev,
                                          float rg, float tg)
{
    const float m = __fmul_rn(0.1f, xt);
    const float s = __fmaf_rn(0.9f, u, m);
    u = __fmaf_rn(-zprev, rg, s);
    const float v = __fadd_rn(u, -bb);

    // unmasked crumb chain (two-use zb stays unfused in XLA)
    const float d   = __fadd_rn(v, -1.0f);
    const float zb  = __fmul_rn(__fmul_rn(-0.5f, __fmul_rn(d, d)), 0.3f);
    const float zsp = __fadd_rn(__fadd_rn(1.0f, -zb), zb);

    const bool p_lt1  = (v < 1.0f);
    const bool p_pos  = (v > 0.0f);
    const bool p_spge = (zsp >= 1.0f);
    const bool fire   = p_pos && (q == 0);

    // fused select: fire&&p_lt1 -> zsp ; fire&&!p_lt1 -> 1.0 ; !fire -> 0.0
    const bool  selsp = fire && p_lt1;
    const float base  = fire ? 1.0f : 0.0f;     // off the zsp chain
    const float z     = selsp ? zsp : base;

    // refractory increment: (z >= 1.0f) == fire && (zsp>=1 || v>=1)
    const bool refr = fire && (p_spge || !p_lt1);
    q = max(q - 1, 0) + (refr ? 5 : 0);

    bb = __fmaf_rn(0.95f, bb, __fmul_rn(__fmul_rn(0.05f, z), tg));
    zprev = z;
    return z;
}

__global__ __launch_bounds__(kThreads, 1)
void full_spike_kernel(const float* __restrict__ x,
                       const float* __restrict__ reset_gamma,
                       const float* __restrict__ thr_gamma,
                       const float* __restrict__ u0,
                       const float* __restrict__ b0,
                       float* __restrict__ out)
{
    __shared__ __align__(16) float buf[3][kBufFloats];   // 48 KB ring

    const int tid = threadIdx.x;
    const int idx = blockIdx.x * kThreads + tid;   // 0 .. kLanes-1
    const int n   = idx & (kN - 1);
    const int b   = idx >> 10;
    const int n0  = (blockIdx.x & 3) * kThreads;   // block's n base (uniform)

    const float* xg = x + (size_t)b * kT * kN + n0;   // block-uniform source
    float* zp = out + (size_t)b * kT * kN + n;

    float u  = u0[n];
    float bb = b0[n];
    const float rg = reset_gamma[n];
    const float tg = thr_gamma[n];
    int   q = 0;
    float zprev = 0.0f;

    const unsigned sbase[3] = { smem_u32(&buf[0][0]), smem_u32(&buf[1][0]),
                                smem_u32(&buf[2][0]) };

    // Per-thread cp.async map: group = 16 rows x 1024 B = 256 thr x 4 x 16 B.
    // chunk c = tid + 256*k : row = c>>6, 16B-col = c&63.
    auto issue_group = [&](int g, int stage) {
        const float* src = xg + (size_t)g * kU * kN;
        const unsigned dst = sbase[stage];
        #pragma unroll
        for (int k = 0; k < 4; ++k) {
            const int c   = tid + kThreads * k;
            const int row = c >> 6;
            const int col = (c & 63) * 16;
            const unsigned d = dst + row * (kThreads * 4) + col;
            const char* s = (const char*)(src + (size_t)row * kN) + col;
            asm volatile("cp.async.cg.shared.global [%0], [%1], 16;"
                         :: "r"(d), "l"(s) : "memory");
        }
        asm volatile("cp.async.commit_group;" ::: "memory");
    };

    // Prime two groups (stages 0 and 1).
    issue_group(0, 0);
    issue_group(1, 1);

    int st_cons = 0;   // stage holding group g
    int st_load = 2;   // stage to load group g+2 into

    for (int g = 0; g < kGroups; ++g) {
        // One commit per iteration (FIFO): wait_group 1 => groups <= g landed
        // (newest outstanding commit G(g+1) may still be in flight -- we only
        // ever read group g below).
        asm volatile("cp.async.wait_group 1;" ::: "memory");
        __syncthreads();   // all threads done reading stage st_load's old data

        if (g + 2 < kGroups) issue_group(g + 2, st_load);
        else asm volatile("cp.async.commit_group;" ::: "memory");  // empty

        const float* bc = &buf[st_cons][0];
        float* zg = zp + (size_t)g * kU * kN;

        // Re-prime lookahead from group g (safe); in-group lookahead only.
        float xt = bc[tid];
        #pragma unroll
        for (int i = 0; i < kU; ++i) {
            const float xt_nx = (i + 1 < kU) ? bc[(i + 1) * kThreads + tid]
                                             : 0.0f;
            __stcs(zg + (size_t)i * kN,
                   lif_step(xt, u, bb, q, zprev, rg, tg));
            xt = xt_nx;
        }

        st_cons = (st_cons == 2) ? 0 : st_cons + 1;
        st_load = (st_load == 2) ? 0 : st_load + 1;
    }
}

extern "C" void kernel_launch(void* const* d_in, const int* in_sizes, int n_in,
                              void* d_out, int out_size)
{
    const float* x           = (const float*)d_in[0];
    const float* reset_gamma = (const float*)d_in[1];
    const float* thr_gamma   = (const float*)d_in[2];
    const float* u0          = (const float*)d_in[3];
    const float* b0          = (const float*)d_in[4];
    float* out = (float*)d_out;

    full_spike_kernel<<<kBlocks, kThreads>>>(x, reset_gamma, thr_gamma, u0, b0, out);
}

// round 17
// speedup vs baseline: 1.0570x; 1.0570x over previous
#include <cuda_runtime.h>

// FullSpikeFunction: LIF recurrence with adaptive threshold + refractory.
// x[B=16, T=4096, N=1024] fp32 -> z[B, T, N] fp32.
//
// Numerics contract (validated rel_err==0.0 R7-R16): XLA fuses the LHS fmul
// of each fadd/fsub (one-use only); the two-use spike crumb stays unfused;
// q uses f32->s32 truncation semantics. See lif_step.
//
// Perf history: warp-level interleaving loses (R16: 2 warps/SMSP = 109
// cyc/step vs R14's 98 at 1 warp/SMSP -- each warp adds work equal to its
// fill). With 1 lane/thread, ~all slots sit on one 36-cyc serial cycle
// (issue 32%). Fix: ILP-2 -- two independent lanes per thread (float2).
// Two chains interleave in one warp; binding term becomes the fma-pipe
// occupancy (~26 ops x rt2 ~= 52 cyc/step) instead of 98.
// Config: 64 blocks x 128 threads = 1 warp/SMSP on 64 SMs; cp.async 3-stage
// SMEM ring (race-free R16 protocol: consume ONLY the landed group).

namespace {
constexpr int kB = 16;
constexpr int kT = 4096;
constexpr int kN = 1024;
constexpr int kU = 16;                     // time steps per group
constexpr int kThreads = 128;
constexpr int kNPerBlk = 256;              // n-columns per block (2 per thread)
constexpr int kBlocks = (kB * kN) / (kThreads * 2);  // 64
constexpr int kGroups = kT / kU;           // 256
constexpr int kBufFloats = kU * kNPerBlk;  // 4096 floats = 16 KB per stage
}  // namespace

__device__ __forceinline__ unsigned smem_u32(const void* p) {
    unsigned r;
    asm("{ .reg .u64 t; cvta.to.shared.u64 t, %1; cvt.u32.u64 %0, t; }"
        : "=r"(r) : "l"(p));
    return r;
}

// One time-step for one scalar lane, exact reference rounding
// (validated rel_err == 0.0 across R7-R16).
__device__ __forceinline__ float lif_step(float xt, float& u, float& bb,
                                          int& q, float& zprev,
                                          float rg, float tg)
{
    const float m = __fmul_rn(0.1f, xt);
    const float s = __fmaf_rn(0.9f, u, m);
    u = __fmaf_rn(-zprev, rg, s);
    const float v = __fadd_rn(u, -bb);

    // unmasked crumb chain (two-use zb stays unfused in XLA)
    const float d   = __fadd_rn(v, -1.0f);
    const float zb  = __fmul_rn(__fmul_rn(-0.5f, __fmul_rn(d, d)), 0.3f);
    const float zsp = __fadd_rn(__fadd_rn(1.0f, -zb), zb);

    const bool p_lt1  = (v < 1.0f);
    const bool p_pos  = (v > 0.0f);
    const bool p_spge = (zsp >= 1.0f);
    const bool fire   = p_pos && (q == 0);

    // fused select: fire&&p_lt1 -> zsp ; fire&&!p_lt1 -> 1.0 ; !fire -> 0.0
    const bool  selsp = fire && p_lt1;
    const float base  = fire ? 1.0f : 0.0f;     // off the zsp chain
    const float z     = selsp ? zsp : base;

    // refractory increment: (z >= 1.0f) == fire && (zsp>=1 || v>=1)
    const bool refr = fire && (p_spge || !p_lt1);
    q = max(q - 1, 0) + (refr ? 5 : 0);

    bb = __fmaf_rn(0.95f, bb, __fmul_rn(__fmul_rn(0.05f, z), tg));
    zprev = z;
    return z;
}

__global__ __launch_bounds__(kThreads, 1)
void full_spike_kernel(const float* __restrict__ x,
                       const float* __restrict__ reset_gamma,
                       const float* __restrict__ thr_gamma,
                       const float* __restrict__ u0,
                       const float* __restrict__ b0,
                       float* __restrict__ out)
{
    __shared__ __align__(16) float buf[3][kBufFloats];   // 48 KB ring

    const int tid = threadIdx.x;
    const int b   = blockIdx.x >> 2;               // batch 0..15
    const int n0  = (blockIdx.x & 3) * kNPerBlk;   // block's n base
    const int n   = n0 + 2 * tid;                  // this thread's lane pair

    const float* xg = x + (size_t)b * kT * kN + n0;   // block-uniform source
    const float2* zbase =
        (const float2*)(out + (size_t)b * kT * kN + n0) + tid;

    // per-lane state (x = lane n, y = lane n+1)
    float ux = u0[n],  uy = u0[n + 1];
    float bx = b0[n],  by = b0[n + 1];
    const float rgx = reset_gamma[n], rgy = reset_gamma[n + 1];
    const float tgx = thr_gamma[n],   tgy = thr_gamma[n + 1];
    int   qx = 0,  qy = 0;
    float zpx = 0.0f, zpy = 0.0f;

    const unsigned sbase[3] = { smem_u32(&buf[0][0]), smem_u32(&buf[1][0]),
                                smem_u32(&buf[2][0]) };

    // cp.async map: group = 16 rows x 1024 B = 128 thr x 8 x 16 B.
    // chunk c = tid + 128*k : row = c>>6, 16B-col = c&63.
    auto issue_group = [&](int g, int stage) {
        const float* src = xg + (size_t)g * kU * kN;
        const unsigned dst = sbase[stage];
        #pragma unroll
        for (int k = 0; k < 8; ++k) {
            const int c   = tid + kThreads * k;
            const int row = c >> 6;
            const int col = (c & 63) * 16;
            const unsigned d = dst + row * (kNPerBlk * 4) + col;
            const char* s = (const char*)(src + (size_t)row * kN) + col;
            asm volatile("cp.async.cg.shared.global [%0], [%1], 16;"
                         :: "r"(d), "l"(s) : "memory");
        }
        asm volatile("cp.async.commit_group;" ::: "memory");
    };

    // Prime two groups (stages 0 and 1).
    issue_group(0, 0);
    issue_group(1, 1);

    int st_cons = 0;   // stage holding group g
    int st_load = 2;   // stage to load group g+2 into

    for (int g = 0; g < kGroups; ++g) {
        // wait_group 1 => groups <= g landed (G(g+1) may be in flight; we
        // only read group g below -- race-free per R15 post-mortem).
        asm volatile("cp.async.wait_group 1;" ::: "memory");
        __syncthreads();   // all threads done reading stage st_load's old data

        if (g + 2 < kGroups) issue_group(g + 2, st_load);
        else asm volatile("cp.async.commit_group;" ::: "memory");  // empty

        const float2* bc = (const float2*)&buf[st_cons][0] + tid;
        const float2* zg = zbase + (size_t)g * kU * (kN / 2);

        // In-group 1-step lookahead only (group g is guaranteed landed).
        float2 xt = bc[0];
        #pragma unroll
        for (int i = 0; i < kU; ++i) {
            const float2 xt_nx = (i + 1 < kU)
                ? bc[(size_t)(i + 1) * (kNPerBlk / 2)]
                : make_float2(0.0f, 0.0f);

            float2 z;
            z.x = lif_step(xt.x, ux, bx, qx, zpx, rgx, tgx);
            z.y = lif_step(xt.y, uy, by, qy, zpy, rgy, tgy);
            __stcs((float2*)(zg + (size_t)i * (kN / 2)), z);
            xt = xt_nx;
        }

        st_cons = (st_cons == 2) ? 0 : st_cons + 1;
        st_load = (st_load == 2) ? 0 : st_load + 1;
    }
}

extern "C" void kernel_launch(void* const* d_in, const int* in_sizes, int n_in,
                              void* d_out, int out_size)
{
    const float* x           = (const float*)d_in[0];
    const float* reset_gamma = (const float*)d_in[1];
    const float* thr_gamma   = (const float*)d_in[2];
    const float* u0          = (const float*)d_in[3];
    const float* b0          = (const float*)d_in[4];
    float* out = (float*)d_out;

    full_spike_kernel<<<kBlocks, kThreads>>>(x, reset_gamma, thr_gamma, u0, b0, out);
}